// round 2
// baseline (speedup 1.0000x reference)
#include <cuda_runtime.h>

#define NPTS   262144
#define HDIM   256
#define RDIM   32
#define TILE   64
#define NTHR   256
#define HPAD   260      // h-row stride (multiple of 4, bank-friendly)
#define WPAD   36       // weight row stride (multiple of 4, bank-friendly)

#define HS_FLOATS (TILE * HPAD)     // 16640
#define WS_FLOATS (HDIM * WPAD)     // 9216
#define US_FLOATS (TILE * WPAD)     // 2304
#define SMEM_BYTES ((HS_FLOATS + WS_FLOATS + US_FLOATS) * 4)   // 112640 B

// tanh via ex2.approx + rcp.approx: abs err ~1e-6, 2 MUFU ops, no branches.
__device__ __forceinline__ float fast_tanh(float x) {
    float ax = fabsf(x);
    float z  = fminf(ax, 12.0f);
    float e;
    asm("ex2.approx.f32 %0, %1;" : "=f"(e) : "f"(z * 2.8853900817779268f)); // 2*log2(e)
    float r;
    asm("rcp.approx.f32 %0, %1;" : "=f"(r) : "f"(e + 1.0f));
    float tpos = fmaf(-2.0f, r, 1.0f);       // 1 - 2/(e^{2|x|}+1)
    return copysignf(tpos, x);
}

__global__ __launch_bounds__(NTHR, 2)
void lr_pinn_fused_kernel(
    const float* __restrict__ x,   const float* __restrict__ t,
    const float* __restrict__ sw,  const float* __restrict__ sb,
    const float* __restrict__ ew,  const float* __restrict__ eb,
    const float* __restrict__ col0, const float* __restrict__ col1, const float* __restrict__ col2,
    const float* __restrict__ row0, const float* __restrict__ row1, const float* __restrict__ row2,
    const float* __restrict__ al0,  const float* __restrict__ al1,  const float* __restrict__ al2,
    float* __restrict__ out)
{
    extern __shared__ float smem[];
    float* hs = smem;                       // [TILE][HPAD]
    float* ws = hs + HS_FLOATS;             // [HDIM][WPAD]
    float* us = ws + WS_FLOATS;             // [TILE][WPAD]

    const int tid  = threadIdx.x;
    const int n    = tid >> 2;              // 0..63  point within tile
    const int sub  = tid & 3;               // 0..3   sub-worker per point
    const int base = blockIdx.x * TILE;

    float* hrow = &hs[n * HPAD];

    // ---------------- start layer: h = tanh(x*w0 + t*w1 + b) ----------------
    {
        const float xv = x[base + n];
        const float tv = t[base + n];
        #pragma unroll 4
        for (int j = 0; j < HDIM / 4; ++j) {
            int jj = 4 * j + sub;
            float w0 = __ldg(&sw[jj * 2]);
            float w1 = __ldg(&sw[jj * 2 + 1]);
            float b  = __ldg(&sb[jj]);
            hrow[jj] = fast_tanh(fmaf(xv, w0, fmaf(tv, w1, b)));
        }
    }
    __syncthreads();

    const float* cols[3] = {col0, col1, col2};
    const float* rows[3] = {row0, row1, row2};
    const float* alps[3] = {al0, al1, al2};

    for (int blk = 0; blk < 3; ++blk) {
        // ---- stage W1[h][r] = col[h][r] * alpha[r] into ws (stride WPAD) ----
        {
            const float* col = cols[blk];
            const float* alp = alps[blk];
            #pragma unroll 4
            for (int i = tid; i < HDIM * RDIM; i += NTHR) {
                int r = i & (RDIM - 1);
                ws[(i >> 5) * WPAD + r] = __ldg(&col[i]) * __ldg(&alp[r]);
            }
        }
        __syncthreads();

        // ---- GEMM1: u[n][rb..rb+7] = sum_h h[n][h] * W1[h][r] ----
        {
            const int rb = sub * 8;
            float a0 = 0.f, a1 = 0.f, a2 = 0.f, a3 = 0.f;
            float a4 = 0.f, a5 = 0.f, a6 = 0.f, a7 = 0.f;
            #pragma unroll 4
            for (int h4 = 0; h4 < HDIM / 4; ++h4) {
                float4 av = *(const float4*)&hrow[4 * h4];
                #pragma unroll
                for (int k = 0; k < 4; ++k) {
                    float a = (k == 0) ? av.x : (k == 1) ? av.y : (k == 2) ? av.z : av.w;
                    const float4* wv = (const float4*)&ws[(4 * h4 + k) * WPAD + rb];
                    float4 w0 = wv[0], w1 = wv[1];
                    a0 = fmaf(a, w0.x, a0); a1 = fmaf(a, w0.y, a1);
                    a2 = fmaf(a, w0.z, a2); a3 = fmaf(a, w0.w, a3);
                    a4 = fmaf(a, w1.x, a4); a5 = fmaf(a, w1.y, a5);
                    a6 = fmaf(a, w1.z, a6); a7 = fmaf(a, w1.w, a7);
                }
            }
            float4* uo = (float4*)&us[n * WPAD + rb];
            uo[0] = make_float4(a0, a1, a2, a3);
            uo[1] = make_float4(a4, a5, a6, a7);
        }
        __syncthreads();

        // ---- stage W2[j][r] = row[j][r] into ws (stride WPAD) ----
        {
            const float* row = rows[blk];
            #pragma unroll 4
            for (int i = tid; i < HDIM * RDIM; i += NTHR) {
                ws[(i >> 5) * WPAD + (i & (RDIM - 1))] = __ldg(&row[i]);
            }
        }
        __syncthreads();

        // ---- GEMM2 + tanh: h_new[n][j] = tanh(sum_r u[n][r] * W2[j][r]) ----
        {
            float u[RDIM];
            const float4* uv = (const float4*)&us[n * WPAD];
            #pragma unroll
            for (int q = 0; q < 8; ++q) {
                float4 v = uv[q];
                u[4 * q] = v.x; u[4 * q + 1] = v.y; u[4 * q + 2] = v.z; u[4 * q + 3] = v.w;
            }
            #pragma unroll 2
            for (int j = 0; j < HDIM / 4; ++j) {
                int jj = 4 * j + sub;
                const float4* wv = (const float4*)&ws[jj * WPAD];
                float s0 = 0.f, s1 = 0.f, s2 = 0.f, s3 = 0.f;
                #pragma unroll
                for (int q = 0; q < 8; ++q) {
                    float4 w = wv[q];
                    s0 = fmaf(u[4 * q],     w.x, s0);
                    s1 = fmaf(u[4 * q + 1], w.y, s1);
                    s2 = fmaf(u[4 * q + 2], w.z, s2);
                    s3 = fmaf(u[4 * q + 3], w.w, s3);
                }
                hrow[jj] = fast_tanh((s0 + s1) + (s2 + s3));
            }
        }
        __syncthreads();
    }

    // ---------------- end layer: out[n] = sum_j h[n][j]*ew[j] + eb ----------------
    {
        float p = 0.f;
        #pragma unroll 4
        for (int j = 0; j < HDIM / 4; ++j) {
            int jj = 4 * j + sub;
            p = fmaf(hrow[jj], __ldg(&ew[jj]), p);
        }
        // reduce the 4 sub-workers (adjacent lanes in one warp)
        p += __shfl_xor_sync(0xffffffffu, p, 1);
        p += __shfl_xor_sync(0xffffffffu, p, 2);
        if (sub == 0) out[base + n] = p + __ldg(eb);
    }
}

extern "C" void kernel_launch(void* const* d_in, const int* in_sizes, int n_in,
                              void* d_out, int out_size) {
    (void)in_sizes; (void)n_in; (void)out_size;
    const float* x    = (const float*)d_in[0];
    const float* t    = (const float*)d_in[1];
    const float* sw   = (const float*)d_in[2];
    const float* sb   = (const float*)d_in[3];
    const float* ew   = (const float*)d_in[4];
    const float* eb   = (const float*)d_in[5];
    const float* col0 = (const float*)d_in[6];
    const float* col1 = (const float*)d_in[7];
    const float* col2 = (const float*)d_in[8];
    const float* row0 = (const float*)d_in[9];
    const float* row1 = (const float*)d_in[10];
    const float* row2 = (const float*)d_in[11];
    const float* al0  = (const float*)d_in[12];
    const float* al1  = (const float*)d_in[13];
    const float* al2  = (const float*)d_in[14];
    float* out = (float*)d_out;

    cudaFuncSetAttribute(lr_pinn_fused_kernel,
                         cudaFuncAttributeMaxDynamicSharedMemorySize, SMEM_BYTES);
    lr_pinn_fused_kernel<<<NPTS / TILE, NTHR, SMEM_BYTES>>>(
        x, t, sw, sb, ew, eb, col0, col1, col2, row0, row1, row2,
        al0, al1, al2, out);
}

// round 4
// speedup vs baseline: 1.1716x; 1.1716x over previous
#include <cuda_runtime.h>

typedef unsigned long long u64;

#define NPTS 262144
#define TILE 128
#define NTHR 256
#define HPAD 260          // hs row stride: HPAD/4=65 odd -> point rows hit distinct bank groups
#define HT   260          // w1t (transposed W1) row stride
#define WPAD 36

#define HS_OFF  0
#define HS_SZ   (TILE*HPAD)          // 33280
#define W1T_OFF (HS_OFF + HS_SZ)
#define W1T_SZ  (32*HT)              // 8320
#define W2_OFF  (W1T_OFF + W1T_SZ)
#define W2_SZ   (256*WPAD)           // 9216
#define US_OFF  (W2_OFF + W2_SZ)
#define US_SZ   (TILE*WPAD)          // 4608
#define SMEM_FLOATS (US_OFF + US_SZ) // 55424
#define SMEM_BYTES  (SMEM_FLOATS*4)  // 221696 B

// packed dual-FP32 FMA (sm_100+; ptxas never emits this from C++)
__device__ __forceinline__ u64 fma2(u64 a, u64 b, u64 c) {
    u64 d;
    asm("fma.rn.f32x2 %0, %1, %2, %3;" : "=l"(d) : "l"(a), "l"(b), "l"(c));
    return d;
}
__device__ __forceinline__ float hsum2(u64 v) {
    float lo, hi;
    asm("mov.b64 {%0, %1}, %2;" : "=f"(lo), "=f"(hi) : "l"(v));
    return lo + hi;
}

// tanh via ex2.approx + rcp.approx: abs err ~1e-6, 2 MUFU ops.
__device__ __forceinline__ float fast_tanh(float x) {
    float ax = fabsf(x);
    float z  = fminf(ax, 12.0f);
    float e;
    asm("ex2.approx.f32 %0, %1;" : "=f"(e) : "f"(z * 2.8853900817779268f));
    float r;
    asm("rcp.approx.f32 %0, %1;" : "=f"(r) : "f"(e + 1.0f));
    float tpos = fmaf(-2.0f, r, 1.0f);
    return copysignf(tpos, x);
}

__device__ __forceinline__ void stage_weights(const float* __restrict__ col,
                                              const float* __restrict__ row,
                                              const float* __restrict__ alp,
                                              float* __restrict__ w1t,
                                              float* __restrict__ w2,
                                              int tid) {
    const int r = tid & 31;               // constant per thread
    const float a = __ldg(&alp[r]);
    #pragma unroll
    for (int k = 0; k < 32; ++k) {
        int idx = tid + NTHR * k;         // 8192 elements, coalesced gmem
        int h = idx >> 5;
        w1t[r * HT + h]   = __ldg(&col[idx]) * a;   // transposed: [r][h]
        w2 [h * WPAD + r] = __ldg(&row[idx]);       // [j][r]
    }
}

__global__ __launch_bounds__(NTHR, 1)
void lr_pinn_fused_kernel(
    const float* __restrict__ x,   const float* __restrict__ t,
    const float* __restrict__ sw,  const float* __restrict__ sb,
    const float* __restrict__ ew,  const float* __restrict__ eb,
    const float* __restrict__ col0, const float* __restrict__ col1, const float* __restrict__ col2,
    const float* __restrict__ row0, const float* __restrict__ row1, const float* __restrict__ row2,
    const float* __restrict__ al0,  const float* __restrict__ al1,  const float* __restrict__ al2,
    float* __restrict__ out)
{
    extern __shared__ float sm[];
    float* hsp = sm + HS_OFF;
    float* w1t = sm + W1T_OFF;
    float* w2p = sm + W2_OFF;
    float* usp = sm + US_OFF;

    const int tid  = threadIdx.x;
    const int g    = tid >> 3;          // 0..31; owns points {g, g+32, g+64, g+96}
    const int sub  = tid & 7;           // 0..7
    const int base = blockIdx.x * TILE;

    // ---------------- start layer ----------------
    {
        float xv[4], tv[4];
        #pragma unroll
        for (int i = 0; i < 4; ++i) {
            xv[i] = __ldg(&x[base + 32 * i + g]);
            tv[i] = __ldg(&t[base + 32 * i + g]);
        }
        #pragma unroll
        for (int m = 0; m < 8; ++m) {
            int jj = 4 * (sub + 8 * m);
            float4 wA = __ldg((const float4*)&sw[2 * jj]);
            float4 wB = __ldg((const float4*)&sw[2 * jj + 4]);
            float4 bb = __ldg((const float4*)&sb[jj]);
            #pragma unroll
            for (int i = 0; i < 4; ++i) {
                float4 hv;
                hv.x = fast_tanh(fmaf(xv[i], wA.x, fmaf(tv[i], wA.y, bb.x)));
                hv.y = fast_tanh(fmaf(xv[i], wA.z, fmaf(tv[i], wA.w, bb.y)));
                hv.z = fast_tanh(fmaf(xv[i], wB.x, fmaf(tv[i], wB.y, bb.z)));
                hv.w = fast_tanh(fmaf(xv[i], wB.z, fmaf(tv[i], wB.w, bb.w)));
                *(float4*)&hsp[(32 * i + g) * HPAD + jj] = hv;
            }
        }
    }
    stage_weights(col0, row0, al0, w1t, w2p, tid);
    __syncthreads();

    const float* cols[3] = {col0, col1, col2};
    const float* rows[3] = {row0, row1, row2};
    const float* alps[3] = {al0, al1, al2};

    for (int blk = 0; blk < 3; ++blk) {
        // ---- GEMM1: u[p][r] = sum_h h[p][h]*W1[h][r]; 4pt x 4r per thread, f32x2 over h-pairs ----
        {
            u64 acc[4][4];
            #pragma unroll
            for (int i = 0; i < 4; ++i)
                #pragma unroll
                for (int rr = 0; rr < 4; ++rr) acc[i][rr] = 0ull;

            const float* wbase = w1t + (4 * sub) * HT;
            #pragma unroll 2
            for (int h4 = 0; h4 < 64; ++h4) {
                ulonglong2 wv[4];
                #pragma unroll
                for (int rr = 0; rr < 4; ++rr)
                    wv[rr] = *(const ulonglong2*)(wbase + rr * HT + 4 * h4);   // warp-broadcast
                #pragma unroll
                for (int i = 0; i < 4; ++i) {
                    ulonglong2 hv = *(const ulonglong2*)(hsp + (32 * i + g) * HPAD + 4 * h4);
                    #pragma unroll
                    for (int rr = 0; rr < 4; ++rr) {
                        acc[i][rr] = fma2(hv.x, wv[rr].x, acc[i][rr]);
                        acc[i][rr] = fma2(hv.y, wv[rr].y, acc[i][rr]);
                    }
                }
            }
            #pragma unroll
            for (int i = 0; i < 4; ++i) {
                float4 o;
                o.x = hsum2(acc[i][0]); o.y = hsum2(acc[i][1]);
                o.z = hsum2(acc[i][2]); o.w = hsum2(acc[i][3]);
                *(float4*)&usp[(32 * i + g) * WPAD + 4 * sub] = o;
            }
        }
        __syncthreads();

        // ---- GEMM2: h[p][j] = tanh(sum_r u[p][r]*W2[j][r]); 4pt x 4j subtiles, f32x2 over r-pairs ----
        {
            #pragma unroll 1
            for (int s = 0; s < 8; ++s) {
                u64 acc[4][4];
                #pragma unroll
                for (int i = 0; i < 4; ++i)
                    #pragma unroll
                    for (int jl = 0; jl < 4; ++jl) acc[i][jl] = 0ull;

                #pragma unroll 2
                for (int rc = 0; rc < 8; ++rc) {
                    ulonglong2 uv[4];
                    #pragma unroll
                    for (int i = 0; i < 4; ++i)
                        uv[i] = *(const ulonglong2*)(usp + (32 * i + g) * WPAD + 4 * rc);
                    #pragma unroll
                    for (int jl = 0; jl < 4; ++jl) {
                        int j = 32 * s + 8 * jl + sub;
                        ulonglong2 wv = *(const ulonglong2*)(w2p + j * WPAD + 4 * rc);
                        #pragma unroll
                        for (int i = 0; i < 4; ++i) {
                            acc[i][jl] = fma2(uv[i].x, wv.x, acc[i][jl]);
                            acc[i][jl] = fma2(uv[i].y, wv.y, acc[i][jl]);
                        }
                    }
                }
                #pragma unroll
                for (int jl = 0; jl < 4; ++jl) {
                    int j = 32 * s + 8 * jl + sub;
                    #pragma unroll
                    for (int i = 0; i < 4; ++i)
                        hsp[(32 * i + g) * HPAD + j] = fast_tanh(hsum2(acc[i][jl]));
                }
            }
        }
        __syncthreads();

        if (blk < 2) {
            stage_weights(cols[blk + 1], rows[blk + 1], alps[blk + 1], w1t, w2p, tid);
            __syncthreads();
        }
    }

    // ---------------- end layer ----------------
    {
        float acc[4] = {0.f, 0.f, 0.f, 0.f};
        #pragma unroll
        for (int m = 0; m < 8; ++m) {
            int jj = 4 * (sub + 8 * m);
            float4 e = __ldg((const float4*)&ew[jj]);
            #pragma unroll
            for (int i = 0; i < 4; ++i) {
                float4 hv = *(const float4*)&hsp[(32 * i + g) * HPAD + jj];
                acc[i] = fmaf(hv.x, e.x, acc[i]);
                acc[i] = fmaf(hv.y, e.y, acc[i]);
                acc[i] = fmaf(hv.z, e.z, acc[i]);
                acc[i] = fmaf(hv.w, e.w, acc[i]);
            }
        }
        #pragma unroll
        for (int i = 0; i < 4; ++i) {
            acc[i] += __shfl_xor_sync(0xffffffffu, acc[i], 1);
            acc[i] += __shfl_xor_sync(0xffffffffu, acc[i], 2);
            acc[i] += __shfl_xor_sync(0xffffffffu, acc[i], 4);
        }
        if (sub == 0) {
            float e0 = __ldg(eb);
            #pragma unroll
            for (int i = 0; i < 4; ++i)
                out[base + 32 * i + g] = acc[i] + e0;
        }
    }
}

extern "C" void kernel_launch(void* const* d_in, const int* in_sizes, int n_in,
                              void* d_out, int out_size) {
    (void)in_sizes; (void)n_in; (void)out_size;
    const float* x    = (const float*)d_in[0];
    const float* t    = (const float*)d_in[1];
    const float* sw   = (const float*)d_in[2];
    const float* sb   = (const float*)d_in[3];
    const float* ew   = (const float*)d_in[4];
    const float* eb   = (const float*)d_in[5];
    const float* col0 = (const float*)d_in[6];
    const float* col1 = (const float*)d_in[7];
    const float* col2 = (const float*)d_in[8];
    const float* row0 = (const float*)d_in[9];
    const float* row1 = (const float*)d_in[10];
    const float* row2 = (const float*)d_in[11];
    const float* al0  = (const float*)d_in[12];
    const float* al1  = (const float*)d_in[13];
    const float* al2  = (const float*)d_in[14];
    float* out = (float*)d_out;

    cudaFuncSetAttribute(lr_pinn_fused_kernel,
                         cudaFuncAttributeMaxDynamicSharedMemorySize, SMEM_BYTES);
    lr_pinn_fused_kernel<<<NPTS / TILE, NTHR, SMEM_BYTES>>>(
        x, t, sw, sb, ew, eb, col0, col1, col2, row0, row1, row2,
        al0, al1, al2, out);
}